// round 14
// baseline (speedup 1.0000x reference)
#include <cuda_runtime.h>
#include <cstdint>

// ---------------- problem constants ----------------
#define NB   8
#define NL   4096
#define NDIM 768
#define NH   12
#define ND   64
#define NM   256
#define NTOK (NB * NL)     // 32768
#define NRH  (NTOK * NH)   // 393216
#define FEPS 1.0e-3f
#define RATIO 0.0625f

// ---------------- scratch (static device globals; no allocs) ----------------
__device__ __align__(128) float g_xr [(size_t)NTOK * NDIM];          // 100 MB  x tf32-rounded
__device__ __align__(128) float g_wr [(size_t)2304 * NDIM];          // 7 MB
__device__ __align__(128) float g_pwr[(size_t)NDIM * NDIM];          // 2.4 MB
__device__ __align__(128) float g_pmr[(size_t)NM * ND];              // 64 KB
__device__ __align__(128) float g_qk [(size_t)2 * NRH * ND];         // 200 MB  q|k rounded [sel][bh,l][64]
__device__ __align__(128) float g_qp [(size_t)NRH * NM];             // 402 MB  q_p rounded [bh,l][256]
__device__ __align__(128) float g_kpT[(size_t)NB * NH * NM * NL];    // 402 MB  k_p^T rounded [bh][m][l]
__device__ __align__(128) float g_vT [(size_t)NB * NH * 128 * NL];   // 200 MB  v^T rounded [bh][d|1|0][l]
__device__ __align__(128) float g_kvT[(size_t)NB * NH * 128 * NM];   // 12.6 MB kv^T [bh][n][m] (rna'd in place)
__device__ __align__(128) float g_att[(size_t)NTOK * NDIM];          // 100 MB  att rounded

// ---------------- PTX helpers ----------------
__device__ __forceinline__ uint32_t s2u(const void* p) {
    uint32_t a;
    asm("{ .reg .u64 t; cvta.to.shared.u64 t, %1; cvt.u32.u64 %0, t; }" : "=r"(a) : "l"(p));
    return a;
}
__device__ __forceinline__ void cpa16(uint32_t s, const void* g) {
    asm volatile("cp.async.cg.shared.global [%0], [%1], 16;\n" :: "r"(s), "l"(g));
}
#define CP_COMMIT() asm volatile("cp.async.commit_group;\n" ::: "memory")
#define CP_WAIT(n)  asm volatile("cp.async.wait_group %0;\n" :: "n"(n) : "memory")
#define SW128(o) ((o) ^ (((o) >> 3) & 0x70))

__device__ __forceinline__ void ldsm_x4(uint32_t* r, uint32_t addr) {
    asm volatile("ldmatrix.sync.aligned.m8n8.x4.shared.b16 {%0,%1,%2,%3}, [%4];"
                 : "=r"(r[0]), "=r"(r[1]), "=r"(r[2]), "=r"(r[3]) : "r"(addr));
}
__device__ __forceinline__ void mma_tf32(float* d, const uint32_t* a, uint32_t b0, uint32_t b1) {
    asm volatile(
        "mma.sync.aligned.m16n8k8.row.col.f32.tf32.tf32.f32 "
        "{%0,%1,%2,%3}, {%4,%5,%6,%7}, {%8,%9}, {%0,%1,%2,%3};"
        : "+f"(d[0]), "+f"(d[1]), "+f"(d[2]), "+f"(d[3])
        : "r"(a[0]), "r"(a[1]), "r"(a[2]), "r"(a[3]), "r"(b0), "r"(b1));
}
__device__ __forceinline__ float rna(float v) {
    uint32_t u;
    asm("cvt.rna.tf32.f32 %0, %1;" : "=r"(u) : "f"(v));
    return __uint_as_float(u);
}

// ---------------- zero / init ----------------
__global__ void zero_kernel(float* __restrict__ p, int n) {
    int i = blockIdx.x * blockDim.x + threadIdx.x;
    if (i < n) p[i] = 0.0f;
}
// g_vT rows 64..79 only (rows 80..127 are never read by the skip-aware K3):
// row 64 = ones (k_sum column), rows 65..79 = zero.
__global__ void initvt_kernel() {
    const int total = NB * NH * 16 * (NL / 4);
    for (int i = blockIdx.x * blockDim.x + threadIdx.x; i < total; i += gridDim.x * blockDim.x) {
        int lp = i & (NL / 4 - 1);
        int rp = i >> 10;
        int row = rp & 15;
        int bh = rp >> 4;
        float v = (row == 0) ? 1.0f : 0.0f;
        *(float4*)(g_vT + ((size_t)bh * 128 + 64 + row) * NL + lp * 4) = make_float4(v, v, v, v);
    }
}

// ---------------- fp32 -> tf32-rounded (RNA); src==dst allowed ----------------
__global__ void rna4_kernel(const float* __restrict__ src, float* __restrict__ dst, int total4) {
    for (int i = blockIdx.x * blockDim.x + threadIdx.x; i < total4; i += gridDim.x * blockDim.x) {
        float4 v = *(const float4*)(src + (size_t)i * 4);
        v.x = rna(v.x); v.y = rna(v.y); v.z = rna(v.z); v.w = rna(v.w);
        *(float4*)(dst + (size_t)i * 4) = v;
    }
}

// ---------------- 1xTF32 GEMM via mma.sync ----------------
// Tile BM=BN=128, BK=32 fp32. 128 thr = 4 warps (2m x 2n), warp tile 64x64.
// 3-stage cp.async, distance-2 prefetch, single sync per chunk,
// per-warp fragment double-buffering. SW128 smem, ldmatrix.
// Asymmetric padding skip: MODE 3 wn==1 computes only ni=0 (den column
// block, cols 64..71); MODE 6 wm==1 computes only mi=0 (rows 64..79,
// the ones-row block). All skipped outputs are never read.
// MODE 0: C = acc + bias (final)                        [K5]
// MODE 2: qkv scatter: q,k rounded -> g_qk; v^T -> g_vT [K1]
// MODE 3: attn: den=col64, divide, rounded -> g_att     [K4]
// MODE 4: relu rounded -> g_qp                          [K2-q]
// MODE 5: relu rounded, transposed -> g_kpT             [K2-k]
// MODE 6: kv^T split-K atomic accumulate -> g_kvT       [K3]
template <int MODE>
__global__ __launch_bounds__(128, 2) void mma_gemm(
    const float* __restrict__ A, int lda, size_t aZ,
    const float* __restrict__ B, int ldb, size_t bZ,
    float* __restrict__ C, int ldc,
    const float* __restrict__ bias,
    int kdim)
{
    extern __shared__ char dynsm[];
    __shared__ float den_sh[128];
    const uint32_t sbase = (s2u(dynsm) + 1023u) & ~1023u;
    const int tid = threadIdx.x;
    const int wid = tid >> 5, lid = tid & 31;
    const int wm = wid & 1, wn = wid >> 1;
    const int n0 = blockIdx.x * 128;
    const int m0 = blockIdx.y * 128;
    int kv_bh = 0;
    if (MODE == 6) {
        kv_bh = blockIdx.z >> 3;
        int seg = blockIdx.z & 7;
        A = g_vT  + (size_t)kv_bh * 128 * NL + seg * 512;   // rows = n (128, 65..127 pad)
        B = g_kpT + (size_t)kv_bh * NM * NL  + seg * 512;   // rows = m (256, 2 x-tiles)
    } else {
        A += (size_t)blockIdx.z * aZ;
        B += (size_t)blockIdx.z * bZ;
    }
    const int NC = kdim >> 5;

    // warp-uniform skip flags
    const bool skipA = (MODE == 6 && wm == 1);   // only mi=0 live
    const bool skipB = (MODE == 3 && wn == 1);   // only ni=0 live

    float acc[4][8][4];
#pragma unroll
    for (int i = 0; i < 4; i++)
#pragma unroll
        for (int j = 0; j < 8; j++)
#pragma unroll
            for (int q = 0; q < 4; q++) acc[i][j][q] = 0.0f;

    auto load_chunk = [&](int c) {
        int slot = c % 3;
        uint32_t ab = sbase + (uint32_t)slot * 32768u;
        uint32_t bb = ab + 16384u;
        const float* ap = A + (size_t)m0 * lda + c * 32;
        const float* bp = B + (size_t)n0 * ldb + c * 32;
#pragma unroll
        for (int i = 0; i < 8; i++) {
            int idx = tid + (i << 7);
            int row = idx >> 3, ch = idx & 7;
            cpa16(ab + SW128(row * 128 + ch * 16), ap + (size_t)row * lda + ch * 4);
        }
#pragma unroll
        for (int i = 0; i < 8; i++) {
            int idx = tid + (i << 7);
            int row = idx >> 3, ch = idx & 7;
            cpa16(bb + SW128(row * 128 + ch * 16), bp + (size_t)row * ldb + ch * 4);
        }
    };

    // preload chunks 0,1 (distance-2 pipeline)
    load_chunk(0); CP_COMMIT();
    if (NC > 1) { load_chunk(1); CP_COMMIT(); }

    const int lt = lid >> 3;
    const int lr = lid & 7;
    const int rowa0 = wm * 64 + ((lt & 1) << 3) + lr;
    const int byta  = (lt >> 1) * 16;
    const int rowb0 = wn * 64 + ((lt >> 1) << 3) + lr;
    const int bytb  = (lt & 1) * 16;

    uint32_t afr[2][4][4], bfr[2][4][4];
    auto ld_frags = [&](uint32_t ab, uint32_t bb, int ks, int buf) {
        if (skipA) {
            ldsm_x4(afr[buf][0], ab + SW128(rowa0 * 128 + ks * 32 + byta));
        } else {
#pragma unroll
            for (int mi = 0; mi < 4; mi++) {
                int off = (rowa0 + mi * 16) * 128 + ks * 32 + byta;
                ldsm_x4(afr[buf][mi], ab + SW128(off));
            }
        }
        if (skipB) {
            ldsm_x4(bfr[buf][0], bb + SW128(rowb0 * 128 + ks * 32 + bytb));
        } else {
#pragma unroll
            for (int ng = 0; ng < 4; ng++) {
                int off = (rowb0 + ng * 16) * 128 + ks * 32 + bytb;
                ldsm_x4(bfr[buf][ng], bb + SW128(off));
            }
        }
    };

    for (int c = 0; c < NC; c++) {
        if (c == NC - 1) { CP_WAIT(0); } else { CP_WAIT(1); }
        __syncthreads();   // single barrier: everyone done reading slot (c-1)%3
        if (c + 2 < NC) { load_chunk(c + 2); CP_COMMIT(); }

        uint32_t ab = sbase + (uint32_t)(c % 3) * 32768u;
        uint32_t bb = ab + 16384u;
        ld_frags(ab, bb, 0, 0);
#pragma unroll
        for (int ks = 0; ks < 4; ks++) {
            int cur = ks & 1;
            if (ks < 3) ld_frags(ab, bb, ks + 1, cur ^ 1);
            if (skipB) {
#pragma unroll
                for (int mi = 0; mi < 4; mi++)
                    mma_tf32(acc[mi][0], afr[cur][mi], bfr[cur][0][0], bfr[cur][0][1]);
            } else if (skipA) {
#pragma unroll
                for (int ni = 0; ni < 8; ni++)
                    mma_tf32(acc[0][ni], afr[cur][0],
                             bfr[cur][ni >> 1][(ni & 1) * 2], bfr[cur][ni >> 1][(ni & 1) * 2 + 1]);
            } else {
#pragma unroll
                for (int mi = 0; mi < 4; mi++)
#pragma unroll
                    for (int ni = 0; ni < 8; ni++)
                        mma_tf32(acc[mi][ni], afr[cur][mi],
                                 bfr[cur][ni >> 1][(ni & 1) * 2], bfr[cur][ni >> 1][(ni & 1) * 2 + 1]);
            }
        }
    }

    // ---------------- epilogue ----------------
    const int lrow = lid >> 2;
    const int lcol = (lid & 3) * 2;

    if (MODE == 0) {
#pragma unroll
        for (int mi = 0; mi < 4; mi++) {
#pragma unroll
            for (int ni = 0; ni < 8; ni++) {
                int col = n0 + wn * 64 + ni * 8 + lcol;
                float b0 = bias[col], b1 = bias[col + 1];
                int r0 = m0 + wm * 64 + mi * 16 + lrow;
                *(float2*)(C + (size_t)r0 * ldc + col) =
                    make_float2(acc[mi][ni][0] + b0, acc[mi][ni][1] + b1);
                *(float2*)(C + (size_t)(r0 + 8) * ldc + col) =
                    make_float2(acc[mi][ni][2] + b0, acc[mi][ni][3] + b1);
            }
        }
    } else if (MODE == 4) {
#pragma unroll
        for (int mi = 0; mi < 4; mi++) {
#pragma unroll
            for (int rr = 0; rr < 2; rr++) {
                int r = m0 + wm * 64 + mi * 16 + rr * 8 + lrow;
                float* dst = g_qp + (size_t)r * NM;
#pragma unroll
                for (int ni = 0; ni < 8; ni++) {
                    int m = n0 + wn * 64 + ni * 8 + lcol;
                    float v0 = rna(fmaxf(acc[mi][ni][rr * 2]     * RATIO, 0.0f) + FEPS);
                    float v1 = rna(fmaxf(acc[mi][ni][rr * 2 + 1] * RATIO, 0.0f) + FEPS);
                    *(float2*)(dst + m) = make_float2(v0, v1);
                }
            }
        }
    } else if (MODE == 5) {
        // k_p transposed -> g_kpT[bh][m][l], staged through smem
        __syncthreads();
        float* st = (float*)dynsm;   // [128 l][129]
#pragma unroll
        for (int mi = 0; mi < 4; mi++) {
#pragma unroll
            for (int rr = 0; rr < 2; rr++) {
                int row = wm * 64 + mi * 16 + rr * 8 + lrow;
#pragma unroll
                for (int ni = 0; ni < 8; ni++) {
                    int cl = wn * 64 + ni * 8 + lcol;
                    st[row * 129 + cl]     = rna(fmaxf(acc[mi][ni][rr * 2]     * RATIO, 0.0f) + FEPS);
                    st[row * 129 + cl + 1] = rna(fmaxf(acc[mi][ni][rr * 2 + 1] * RATIO, 0.0f) + FEPS);
                }
            }
        }
        __syncthreads();
        int bh = m0 >> 12, l0 = m0 & (NL - 1);
        float* dst = g_kpT + ((size_t)bh * NM + n0 + tid) * NL + l0;
#pragma unroll
        for (int j = 0; j < 32; j++) {
            float4 o;
            o.x = st[(4 * j + 0) * 129 + tid];
            o.y = st[(4 * j + 1) * 129 + tid];
            o.z = st[(4 * j + 2) * 129 + tid];
            o.w = st[(4 * j + 3) * 129 + tid];
            *(float4*)(dst + 4 * j) = o;
        }
    } else if (MODE == 2) {
        const int region = n0 / 768;               // 0=q, 1=k, 2=v
        if (region < 2) {
            const int h = ((n0 % 768) >> 6) + wn;
#pragma unroll
            for (int mi = 0; mi < 4; mi++) {
#pragma unroll
                for (int rr = 0; rr < 2; rr++) {
                    int r = m0 + wm * 64 + mi * 16 + rr * 8 + lrow;
                    int b = r >> 12, l = r & (NL - 1);
                    float* dst = g_qk +
                        ((size_t)region * NRH + (size_t)(b * NH + h) * NL + l) * ND;
#pragma unroll
                    for (int ni = 0; ni < 8; ni++) {
                        int d = ni * 8 + lcol;
                        int col = n0 + wn * 64 + d;
                        float v0 = rna(acc[mi][ni][rr * 2]     + bias[col]);
                        float v1 = rna(acc[mi][ni][rr * 2 + 1] + bias[col + 1]);
                        *(float2*)(dst + d) = make_float2(v0, v1);
                    }
                }
            }
        } else {
            // v transposed -> g_vT[bh][d][l], staged through smem
            __syncthreads();
            float* st = (float*)dynsm;   // [128 tok][129]
#pragma unroll
            for (int mi = 0; mi < 4; mi++) {
#pragma unroll
                for (int rr = 0; rr < 2; rr++) {
                    int row = wm * 64 + mi * 16 + rr * 8 + lrow;
#pragma unroll
                    for (int ni = 0; ni < 8; ni++) {
                        int cl = wn * 64 + ni * 8 + lcol;
                        int col = n0 + cl;
                        st[row * 129 + cl]     = rna(acc[mi][ni][rr * 2]     + bias[col]);
                        st[row * 129 + cl + 1] = rna(acc[mi][ni][rr * 2 + 1] + bias[col + 1]);
                    }
                }
            }
            __syncthreads();
            int b = m0 >> 12, l0 = m0 & (NL - 1);
            int head = ((n0 - 1536) >> 6) + (tid >> 6);
            float* dst = g_vT + ((size_t)(b * NH + head) * 128 + (tid & 63)) * NL + l0;
#pragma unroll
            for (int j = 0; j < 32; j++) {
                float4 o;
                o.x = st[(4 * j + 0) * 129 + tid];
                o.y = st[(4 * j + 1) * 129 + tid];
                o.z = st[(4 * j + 2) * 129 + tid];
                o.w = st[(4 * j + 3) * 129 + tid];
                *(float4*)(dst + 4 * j) = o;
            }
        }
    } else if (MODE == 6) {
        // C = kv^T [n][m]: rows = n, cols = m (n0 selects half of 256)
        float* dst = g_kvT + (size_t)kv_bh * 128 * NM;
        const int MImax = skipA ? 1 : 4;
        for (int mi = 0; mi < MImax; mi++) {
#pragma unroll
            for (int ni = 0; ni < 8; ni++) {
                int colx = n0 + wn * 64 + ni * 8 + lcol;
                int r0 = wm * 64 + mi * 16 + lrow;
                atomicAdd(dst + (size_t)r0 * NM + colx,           acc[mi][ni][0]);
                atomicAdd(dst + (size_t)r0 * NM + colx + 1,       acc[mi][ni][1]);
                atomicAdd(dst + (size_t)(r0 + 8) * NM + colx,     acc[mi][ni][2]);
                atomicAdd(dst + (size_t)(r0 + 8) * NM + colx + 1, acc[mi][ni][3]);
            }
        }
    } else if (MODE == 3) {
        // attn: den = col 64 (wn==1, ni==0, lcol==0), divide, write g_att
        if (wn == 1 && (lid & 3) == 0) {
#pragma unroll
            for (int mi = 0; mi < 4; mi++)
#pragma unroll
                for (int rr = 0; rr < 2; rr++)
                    den_sh[wm * 64 + mi * 16 + rr * 8 + lrow] = acc[mi][0][rr * 2];
        }
        __syncthreads();
        if (wn == 0) {
            const int bh = blockIdx.z;
            const int b = bh / NH, h = bh - b * NH;
#pragma unroll
            for (int mi = 0; mi < 4; mi++) {
#pragma unroll
                for (int rr = 0; rr < 2; rr++) {
                    int rloc = wm * 64 + mi * 16 + rr * 8 + lrow;
                    int token = b * NL + m0 + rloc;
                    float inv = 1.0f / den_sh[rloc];
                    float* dst = g_att + (size_t)token * NDIM + h * ND;
#pragma unroll
                    for (int ni = 0; ni < 8; ni++) {
                        int d = ni * 8 + lcol;
                        float v0 = rna(acc[mi][ni][rr * 2]     * inv);
                        float v1 = rna(acc[mi][ni][rr * 2 + 1] * inv);
                        *(float2*)(dst + d) = make_float2(v0, v1);
                    }
                }
            }
        }
    }
}

// ---------------- launch ----------------
extern "C" void kernel_launch(void* const* d_in, const int* in_sizes, int n_in,
                              void* d_out, int out_size)
{
    const float* x        = (const float*)d_in[0];
    const float* qkv_w    = (const float*)d_in[1];
    const float* qkv_b    = (const float*)d_in[2];
    const float* proj_w   = (const float*)d_in[3];
    const float* proj_b   = (const float*)d_in[4];
    const float* proj_mat = (const float*)d_in[5];
    float* out = (float*)d_out;

    float *xr_p, *wr_p, *pwr_p, *pmr_p, *qk_p, *qp_p, *kvt_p, *att_p;
    cudaGetSymbolAddress((void**)&xr_p,  g_xr);
    cudaGetSymbolAddress((void**)&wr_p,  g_wr);
    cudaGetSymbolAddress((void**)&pwr_p, g_pwr);
    cudaGetSymbolAddress((void**)&pmr_p, g_pmr);
    cudaGetSymbolAddress((void**)&qk_p,  g_qk);
    cudaGetSymbolAddress((void**)&qp_p,  g_qp);
    cudaGetSymbolAddress((void**)&kvt_p, g_kvT);
    cudaGetSymbolAddress((void**)&att_p, g_att);

    const int SMEM_GEMM = 3 * 32768 + 1024;
    cudaFuncSetAttribute(mma_gemm<0>, cudaFuncAttributeMaxDynamicSharedMemorySize, SMEM_GEMM);
    cudaFuncSetAttribute(mma_gemm<2>, cudaFuncAttributeMaxDynamicSharedMemorySize, SMEM_GEMM);
    cudaFuncSetAttribute(mma_gemm<3>, cudaFuncAttributeMaxDynamicSharedMemorySize, SMEM_GEMM);
    cudaFuncSetAttribute(mma_gemm<4>, cudaFuncAttributeMaxDynamicSharedMemorySize, SMEM_GEMM);
    cudaFuncSetAttribute(mma_gemm<5>, cudaFuncAttributeMaxDynamicSharedMemorySize, SMEM_GEMM);
    cudaFuncSetAttribute(mma_gemm<6>, cudaFuncAttributeMaxDynamicSharedMemorySize, SMEM_GEMM);

    // launch 0: round x
    rna4_kernel<<<4096, 256>>>(x, xr_p, NTOK * NDIM / 4);
    // launch 1: round qkv_w
    rna4_kernel<<<1024, 256>>>(qkv_w, wr_p, 2304 * NDIM / 4);
    // launch 2: zero kv^T accumulator
    const int kvn = NB * NH * 128 * NM;
    zero_kernel<<<(kvn + 255) / 256, 256>>>(kvt_p, kvn);

    // launch 3 (profiled): K1 qkv = xr @ qkv_w^T + b; scatter q,k rounded + v^T rounded
    mma_gemm<2><<<dim3(18, NTOK / 128), 128, SMEM_GEMM>>>(
        xr_p, NDIM, 0, wr_p, NDIM, 0, nullptr, 0, qkv_b, NDIM);

    // launch 4: init vT ones/zero rows (64..79 only)
    initvt_kernel<<<1536, 256>>>();
    // launch 5: round proj_mat
    rna4_kernel<<<16, 256>>>(proj_mat, pmr_p, NM * ND / 4);

    // launch 6: K2-k: k_p -> g_kpT (rounded, transposed)
    mma_gemm<5><<<dim3(2, NRH / 128), 128, SMEM_GEMM>>>(
        qk_p + (size_t)NRH * ND, ND, 0, pmr_p, ND, 0, nullptr, 0, nullptr, ND);

    // launch 7: K3: kv^T[bh] = (vT · kpT^T), split-K=8, atomic fp32 -> g_kvT
    mma_gemm<6><<<dim3(2, 1, NB * NH * 8), 128, SMEM_GEMM>>>(
        nullptr, NL, 0, nullptr, NL, 0, nullptr, 0, nullptr, 512);

    // launch 8: round kvT in place (K4 operand)
    rna4_kernel<<<768, 256>>>(kvt_p, kvt_p, kvn / 4);

    // launch 9: K2-q: q_p -> g_qp (rounded)
    mma_gemm<4><<<dim3(2, NRH / 128), 128, SMEM_GEMM>>>(
        qk_p, ND, 0, pmr_p, ND, 0, nullptr, 0, nullptr, ND);

    // launch 10: round proj_w
    rna4_kernel<<<512, 256>>>(proj_w, pwr_p, NDIM * NDIM / 4);

    // launch 11: K4: att = (q_p @ kv) / den -> g_att; z = bh
    mma_gemm<3><<<dim3(1, NL / 128, NB * NH), 128, SMEM_GEMM>>>(
        qp_p, NM, (size_t)NL * NM, kvt_p, NM, (size_t)128 * NM,
        nullptr, 0, nullptr, NM);

    // launch 12: K5: out = att @ proj_w^T + proj_b
    mma_gemm<0><<<dim3(NDIM / 128, NTOK / 128), 128, SMEM_GEMM>>>(
        att_p, NDIM, 0, pwr_p, NDIM, 0, out, NDIM, proj_b, NDIM);
}

// round 15
// speedup vs baseline: 1.0374x; 1.0374x over previous
#include <cuda_runtime.h>
#include <cstdint>

// ---------------- problem constants ----------------
#define NB   8
#define NL   4096
#define NDIM 768
#define NH   12
#define ND   64
#define NM   256
#define NTOK (NB * NL)     // 32768
#define NRH  (NTOK * NH)   // 393216
#define FEPS 1.0e-3f
#define RATIO 0.0625f

// ---------------- scratch (static device globals; no allocs) ----------------
__device__ __align__(128) float g_xr [(size_t)NTOK * NDIM];          // 100 MB  x tf32-rounded
__device__ __align__(128) float g_wr [(size_t)2304 * NDIM];          // 7 MB
__device__ __align__(128) float g_pwr[(size_t)NDIM * NDIM];          // 2.4 MB
__device__ __align__(128) float g_pmr[(size_t)NM * ND];              // 64 KB
__device__ __align__(128) float g_qk [(size_t)2 * NRH * ND];         // 200 MB  q|k rounded [sel][bh,l][64]
__device__ __align__(128) float g_qp [(size_t)NRH * NM];             // 402 MB  q_p rounded [bh,l][256]
__device__ __align__(128) float g_kpT[(size_t)NB * NH * NM * NL];    // 402 MB  k_p^T rounded [bh][m][l]
__device__ __align__(128) float g_vT [(size_t)NB * NH * 128 * NL];   // 200 MB  v^T rounded [bh][d|1|0][l]
__device__ __align__(128) float g_kvT[(size_t)NB * NH * 128 * NM];   // 12.6 MB kv^T [bh][n][m] (rna'd in place)
__device__ __align__(128) float g_att[(size_t)NTOK * NDIM];          // 100 MB  att rounded

// ---------------- PTX helpers ----------------
__device__ __forceinline__ uint32_t s2u(const void* p) {
    uint32_t a;
    asm("{ .reg .u64 t; cvta.to.shared.u64 t, %1; cvt.u32.u64 %0, t; }" : "=r"(a) : "l"(p));
    return a;
}
__device__ __forceinline__ void cpa16(uint32_t s, const void* g) {
    asm volatile("cp.async.cg.shared.global [%0], [%1], 16;\n" :: "r"(s), "l"(g));
}
#define CP_COMMIT() asm volatile("cp.async.commit_group;\n" ::: "memory")
#define CP_WAIT(n)  asm volatile("cp.async.wait_group %0;\n" :: "n"(n) : "memory")
#define SW128(o) ((o) ^ (((o) >> 3) & 0x70))

__device__ __forceinline__ void ldsm_x4(uint32_t* r, uint32_t addr) {
    asm volatile("ldmatrix.sync.aligned.m8n8.x4.shared.b16 {%0,%1,%2,%3}, [%4];"
                 : "=r"(r[0]), "=r"(r[1]), "=r"(r[2]), "=r"(r[3]) : "r"(addr));
}
__device__ __forceinline__ void mma_tf32(float* d, const uint32_t* a, uint32_t b0, uint32_t b1) {
    asm volatile(
        "mma.sync.aligned.m16n8k8.row.col.f32.tf32.tf32.f32 "
        "{%0,%1,%2,%3}, {%4,%5,%6,%7}, {%8,%9}, {%0,%1,%2,%3};"
        : "+f"(d[0]), "+f"(d[1]), "+f"(d[2]), "+f"(d[3])
        : "r"(a[0]), "r"(a[1]), "r"(a[2]), "r"(a[3]), "r"(b0), "r"(b1));
}
__device__ __forceinline__ float rna(float v) {
    uint32_t u;
    asm("cvt.rna.tf32.f32 %0, %1;" : "=r"(u) : "f"(v));
    return __uint_as_float(u);
}

// ---------------- fp32 -> tf32-rounded (RNA); src==dst allowed ----------------
__global__ void rna4_kernel(const float* __restrict__ src, float* __restrict__ dst, int total4) {
    for (int i = blockIdx.x * blockDim.x + threadIdx.x; i < total4; i += gridDim.x * blockDim.x) {
        float4 v = *(const float4*)(src + (size_t)i * 4);
        v.x = rna(v.x); v.y = rna(v.y); v.z = rna(v.z); v.w = rna(v.w);
        *(float4*)(dst + (size_t)i * 4) = v;
    }
}

// ---------------- consolidated prep: round w/pw/pm, zero kvT, init vT rows ----------------
#define W4   (2304 * NDIM / 4)            // 442368
#define PW4  (NDIM * NDIM / 4)            // 147456
#define PM4  (NM * ND / 4)                // 4096
#define KV4  (NB * NH * 128 * NM / 4)     // 786432
#define VT4  (NB * NH * 16 * (NL / 4))    // 1572864
#define PREP_TOT (W4 + PW4 + PM4 + KV4 + VT4)

__global__ void prep_kernel(const float* __restrict__ qkv_w,
                            const float* __restrict__ proj_w,
                            const float* __restrict__ proj_mat) {
    for (int i = blockIdx.x * blockDim.x + threadIdx.x; i < PREP_TOT; i += gridDim.x * blockDim.x) {
        if (i < W4) {
            float4 v = *(const float4*)(qkv_w + (size_t)i * 4);
            v.x = rna(v.x); v.y = rna(v.y); v.z = rna(v.z); v.w = rna(v.w);
            *(float4*)(g_wr + (size_t)i * 4) = v;
        } else if (i < W4 + PW4) {
            int j = i - W4;
            float4 v = *(const float4*)(proj_w + (size_t)j * 4);
            v.x = rna(v.x); v.y = rna(v.y); v.z = rna(v.z); v.w = rna(v.w);
            *(float4*)(g_pwr + (size_t)j * 4) = v;
        } else if (i < W4 + PW4 + PM4) {
            int j = i - W4 - PW4;
            float4 v = *(const float4*)(proj_mat + (size_t)j * 4);
            v.x = rna(v.x); v.y = rna(v.y); v.z = rna(v.z); v.w = rna(v.w);
            *(float4*)(g_pmr + (size_t)j * 4) = v;
        } else if (i < W4 + PW4 + PM4 + KV4) {
            int j = i - W4 - PW4 - PM4;
            *(float4*)(g_kvT + (size_t)j * 4) = make_float4(0.f, 0.f, 0.f, 0.f);
        } else {
            int j = i - W4 - PW4 - PM4 - KV4;   // [96][16][1024 float4s]
            int lp = j & (NL / 4 - 1);
            int rp = j >> 10;
            int row = rp & 15;
            int bh = rp >> 4;
            float v = (row == 0) ? 1.0f : 0.0f;
            *(float4*)(g_vT + ((size_t)bh * 128 + 64 + row) * NL + lp * 4) = make_float4(v, v, v, v);
        }
    }
}

// ---------------- 1xTF32 GEMM via mma.sync ----------------
// Tile BM=BN=128, BK=32 fp32. 128 thr = 4 warps (2m x 2n), warp tile 64x64.
// 3-stage cp.async, distance-2 prefetch, single sync per chunk,
// per-warp fragment double-buffering. SW128 smem, ldmatrix.
// MODE 0: C = acc + bias (final)                        [K5]
// MODE 2: qkv scatter: q,k rounded -> g_qk; v^T -> g_vT [K1]
// MODE 3: attn: den=col64, divide, rounded -> g_att     [K4]
// MODE 6: kv^T split-K atomic accumulate -> g_kvT       [K3]
// MODE 7: merged K2: z=0 -> q_p (g_qp); z=1 -> k_p^T (g_kpT)
template <int MODE>
__global__ __launch_bounds__(128, 2) void mma_gemm(
    const float* __restrict__ A, int lda, size_t aZ,
    const float* __restrict__ B, int ldb, size_t bZ,
    float* __restrict__ C, int ldc,
    const float* __restrict__ bias,
    int kdim)
{
    extern __shared__ char dynsm[];
    __shared__ float den_sh[128];
    const uint32_t sbase = (s2u(dynsm) + 1023u) & ~1023u;
    const int tid = threadIdx.x;
    const int wid = tid >> 5, lid = tid & 31;
    const int wm = wid & 1, wn = wid >> 1;
    const int n0 = blockIdx.x * 128;
    const int m0 = blockIdx.y * 128;
    int kv_bh = 0;
    if (MODE == 6) {
        kv_bh = blockIdx.z >> 3;
        int seg = blockIdx.z & 7;
        A = g_vT  + (size_t)kv_bh * 128 * NL + seg * 512;   // rows = n (128)
        B = g_kpT + (size_t)kv_bh * NM * NL  + seg * 512;   // rows = m (256, 2 x-tiles)
    } else {
        A += (size_t)blockIdx.z * aZ;
        B += (size_t)blockIdx.z * bZ;
    }
    const int NC = kdim >> 5;

    float acc[4][8][4];
#pragma unroll
    for (int i = 0; i < 4; i++)
#pragma unroll
        for (int j = 0; j < 8; j++)
#pragma unroll
            for (int q = 0; q < 4; q++) acc[i][j][q] = 0.0f;

    auto load_chunk = [&](int c) {
        int slot = c % 3;
        uint32_t ab = sbase + (uint32_t)slot * 32768u;
        uint32_t bb = ab + 16384u;
        const float* ap = A + (size_t)m0 * lda + c * 32;
        const float* bp = B + (size_t)n0 * ldb + c * 32;
#pragma unroll
        for (int i = 0; i < 8; i++) {
            int idx = tid + (i << 7);
            int row = idx >> 3, ch = idx & 7;
            cpa16(ab + SW128(row * 128 + ch * 16), ap + (size_t)row * lda + ch * 4);
        }
#pragma unroll
        for (int i = 0; i < 8; i++) {
            int idx = tid + (i << 7);
            int row = idx >> 3, ch = idx & 7;
            cpa16(bb + SW128(row * 128 + ch * 16), bp + (size_t)row * ldb + ch * 4);
        }
    };

    // preload chunks 0,1 (distance-2 pipeline)
    load_chunk(0); CP_COMMIT();
    if (NC > 1) { load_chunk(1); CP_COMMIT(); }

    const int lt = lid >> 3;
    const int lr = lid & 7;
    const int rowa0 = wm * 64 + ((lt & 1) << 3) + lr;
    const int byta  = (lt >> 1) * 16;
    const int rowb0 = wn * 64 + ((lt >> 1) << 3) + lr;
    const int bytb  = (lt & 1) * 16;

    uint32_t afr[2][4][4], bfr[2][4][4];
    auto ld_frags = [&](uint32_t ab, uint32_t bb, int ks, int buf) {
#pragma unroll
        for (int mi = 0; mi < 4; mi++) {
            int off = (rowa0 + mi * 16) * 128 + ks * 32 + byta;
            ldsm_x4(afr[buf][mi], ab + SW128(off));
        }
#pragma unroll
        for (int ng = 0; ng < 4; ng++) {
            int off = (rowb0 + ng * 16) * 128 + ks * 32 + bytb;
            ldsm_x4(bfr[buf][ng], bb + SW128(off));
        }
    };

    for (int c = 0; c < NC; c++) {
        if (c == NC - 1) { CP_WAIT(0); } else { CP_WAIT(1); }
        __syncthreads();   // single barrier: everyone done reading slot (c-1)%3
        if (c + 2 < NC) { load_chunk(c + 2); CP_COMMIT(); }

        uint32_t ab = sbase + (uint32_t)(c % 3) * 32768u;
        uint32_t bb = ab + 16384u;
        ld_frags(ab, bb, 0, 0);
#pragma unroll
        for (int ks = 0; ks < 4; ks++) {
            int cur = ks & 1;
            if (ks < 3) ld_frags(ab, bb, ks + 1, cur ^ 1);
#pragma unroll
            for (int mi = 0; mi < 4; mi++)
#pragma unroll
                for (int ni = 0; ni < 8; ni++)
                    mma_tf32(acc[mi][ni], afr[cur][mi],
                             bfr[cur][ni >> 1][(ni & 1) * 2], bfr[cur][ni >> 1][(ni & 1) * 2 + 1]);
        }
    }

    // ---------------- epilogue ----------------
    const int lrow = lid >> 2;
    const int lcol = (lid & 3) * 2;

    if (MODE == 0) {
#pragma unroll
        for (int mi = 0; mi < 4; mi++) {
#pragma unroll
            for (int ni = 0; ni < 8; ni++) {
                int col = n0 + wn * 64 + ni * 8 + lcol;
                float b0 = bias[col], b1 = bias[col + 1];
                int r0 = m0 + wm * 64 + mi * 16 + lrow;
                *(float2*)(C + (size_t)r0 * ldc + col) =
                    make_float2(acc[mi][ni][0] + b0, acc[mi][ni][1] + b1);
                *(float2*)(C + (size_t)(r0 + 8) * ldc + col) =
                    make_float2(acc[mi][ni][2] + b0, acc[mi][ni][3] + b1);
            }
        }
    } else if (MODE == 7) {
        if (blockIdx.z == 0) {
            // q_p -> g_qp (rounded)
#pragma unroll
            for (int mi = 0; mi < 4; mi++) {
#pragma unroll
                for (int rr = 0; rr < 2; rr++) {
                    int r = m0 + wm * 64 + mi * 16 + rr * 8 + lrow;
                    float* dst = g_qp + (size_t)r * NM;
#pragma unroll
                    for (int ni = 0; ni < 8; ni++) {
                        int m = n0 + wn * 64 + ni * 8 + lcol;
                        float v0 = rna(fmaxf(acc[mi][ni][rr * 2]     * RATIO, 0.0f) + FEPS);
                        float v1 = rna(fmaxf(acc[mi][ni][rr * 2 + 1] * RATIO, 0.0f) + FEPS);
                        *(float2*)(dst + m) = make_float2(v0, v1);
                    }
                }
            }
        } else {
            // k_p transposed -> g_kpT[bh][m][l], staged through smem
            __syncthreads();
            float* st = (float*)dynsm;   // [128 l][129]
#pragma unroll
            for (int mi = 0; mi < 4; mi++) {
#pragma unroll
                for (int rr = 0; rr < 2; rr++) {
                    int row = wm * 64 + mi * 16 + rr * 8 + lrow;
#pragma unroll
                    for (int ni = 0; ni < 8; ni++) {
                        int cl = wn * 64 + ni * 8 + lcol;
                        st[row * 129 + cl]     = rna(fmaxf(acc[mi][ni][rr * 2]     * RATIO, 0.0f) + FEPS);
                        st[row * 129 + cl + 1] = rna(fmaxf(acc[mi][ni][rr * 2 + 1] * RATIO, 0.0f) + FEPS);
                    }
                }
            }
            __syncthreads();
            int bh = m0 >> 12, l0 = m0 & (NL - 1);
            float* dst = g_kpT + ((size_t)bh * NM + n0 + tid) * NL + l0;
#pragma unroll
            for (int j = 0; j < 32; j++) {
                float4 o;
                o.x = st[(4 * j + 0) * 129 + tid];
                o.y = st[(4 * j + 1) * 129 + tid];
                o.z = st[(4 * j + 2) * 129 + tid];
                o.w = st[(4 * j + 3) * 129 + tid];
                *(float4*)(dst + 4 * j) = o;
            }
        }
    } else if (MODE == 2) {
        const int region = n0 / 768;               // 0=q, 1=k, 2=v
        if (region < 2) {
            const int h = ((n0 % 768) >> 6) + wn;
#pragma unroll
            for (int mi = 0; mi < 4; mi++) {
#pragma unroll
                for (int rr = 0; rr < 2; rr++) {
                    int r = m0 + wm * 64 + mi * 16 + rr * 8 + lrow;
                    int b = r >> 12, l = r & (NL - 1);
                    float* dst = g_qk +
                        ((size_t)region * NRH + (size_t)(b * NH + h) * NL + l) * ND;
#pragma unroll
                    for (int ni = 0; ni < 8; ni++) {
                        int d = ni * 8 + lcol;
                        int col = n0 + wn * 64 + d;
                        float v0 = rna(acc[mi][ni][rr * 2]     + bias[col]);
                        float v1 = rna(acc[mi][ni][rr * 2 + 1] + bias[col + 1]);
                        *(float2*)(dst + d) = make_float2(v0, v1);
                    }
                }
            }
        } else {
            // v transposed -> g_vT[bh][d][l], staged through smem
            __syncthreads();
            float* st = (float*)dynsm;   // [128 tok][129]
#pragma unroll
            for (int mi = 0; mi < 4; mi++) {
#pragma unroll
                for (int rr = 0; rr < 2; rr++) {
                    int row = wm * 64 + mi * 16 + rr * 8 + lrow;
#pragma unroll
                    for (int ni = 0; ni < 8; ni++) {
                        int cl = wn * 64 + ni * 8 + lcol;
                        int col = n0 + cl;
                        st[row * 129 + cl]     = rna(acc[mi][ni][rr * 2]     + bias[col]);
                        st[row * 129 + cl + 1] = rna(acc[mi][ni][rr * 2 + 1] + bias[col + 1]);
                    }
                }
            }
            __syncthreads();
            int b = m0 >> 12, l0 = m0 & (NL - 1);
            int head = ((n0 - 1536) >> 6) + (tid >> 6);
            float* dst = g_vT + ((size_t)(b * NH + head) * 128 + (tid & 63)) * NL + l0;
#pragma unroll
            for (int j = 0; j < 32; j++) {
                float4 o;
                o.x = st[(4 * j + 0) * 129 + tid];
                o.y = st[(4 * j + 1) * 129 + tid];
                o.z = st[(4 * j + 2) * 129 + tid];
                o.w = st[(4 * j + 3) * 129 + tid];
                *(float4*)(dst + 4 * j) = o;
            }
        }
    } else if (MODE == 6) {
        // C = kv^T [n][m]: rows = n, cols = m (n0 selects half of 256)
        float* dst = g_kvT + (size_t)kv_bh * 128 * NM;
#pragma unroll
        for (int mi = 0; mi < 4; mi++) {
#pragma unroll
            for (int ni = 0; ni < 8; ni++) {
                int colx = n0 + wn * 64 + ni * 8 + lcol;
                int r0 = wm * 64 + mi * 16 + lrow;
                atomicAdd(dst + (size_t)r0 * NM + colx,           acc[mi][ni][0]);
                atomicAdd(dst + (size_t)r0 * NM + colx + 1,       acc[mi][ni][1]);
                atomicAdd(dst + (size_t)(r0 + 8) * NM + colx,     acc[mi][ni][2]);
                atomicAdd(dst + (size_t)(r0 + 8) * NM + colx + 1, acc[mi][ni][3]);
            }
        }
    } else if (MODE == 3) {
        // attn: den = col 64 (wn==1, ni==0, lcol==0), divide, write g_att
        if (wn == 1 && (lid & 3) == 0) {
#pragma unroll
            for (int mi = 0; mi < 4; mi++)
#pragma unroll
                for (int rr = 0; rr < 2; rr++)
                    den_sh[wm * 64 + mi * 16 + rr * 8 + lrow] = acc[mi][0][rr * 2];
        }
        __syncthreads();
        if (wn == 0) {
            const int bh = blockIdx.z;
            const int b = bh / NH, h = bh - b * NH;
#pragma unroll
            for (int mi = 0; mi < 4; mi++) {
#pragma unroll
                for (int rr = 0; rr < 2; rr++) {
                    int rloc = wm * 64 + mi * 16 + rr * 8 + lrow;
                    int token = b * NL + m0 + rloc;
                    float inv = 1.0f / den_sh[rloc];
                    float* dst = g_att + (size_t)token * NDIM + h * ND;
#pragma unroll
                    for (int ni = 0; ni < 8; ni++) {
                        int d = ni * 8 + lcol;
                        float v0 = rna(acc[mi][ni][rr * 2]     * inv);
                        float v1 = rna(acc[mi][ni][rr * 2 + 1] * inv);
                        *(float2*)(dst + d) = make_float2(v0, v1);
                    }
                }
            }
        }
    }
}

// ---------------- launch ----------------
extern "C" void kernel_launch(void* const* d_in, const int* in_sizes, int n_in,
                              void* d_out, int out_size)
{
    const float* x        = (const float*)d_in[0];
    const float* qkv_w    = (const float*)d_in[1];
    const float* qkv_b    = (const float*)d_in[2];
    const float* proj_w   = (const float*)d_in[3];
    const float* proj_b   = (const float*)d_in[4];
    const float* proj_mat = (const float*)d_in[5];
    float* out = (float*)d_out;

    float *xr_p, *wr_p, *pwr_p, *pmr_p, *qk_p, *qp_p, *kvt_p, *att_p;
    cudaGetSymbolAddress((void**)&xr_p,  g_xr);
    cudaGetSymbolAddress((void**)&wr_p,  g_wr);
    cudaGetSymbolAddress((void**)&pwr_p, g_pwr);
    cudaGetSymbolAddress((void**)&pmr_p, g_pmr);
    cudaGetSymbolAddress((void**)&qk_p,  g_qk);
    cudaGetSymbolAddress((void**)&qp_p,  g_qp);
    cudaGetSymbolAddress((void**)&kvt_p, g_kvT);
    cudaGetSymbolAddress((void**)&att_p, g_att);

    const int SMEM_GEMM = 3 * 32768 + 1024;
    cudaFuncSetAttribute(mma_gemm<0>, cudaFuncAttributeMaxDynamicSharedMemorySize, SMEM_GEMM);
    cudaFuncSetAttribute(mma_gemm<2>, cudaFuncAttributeMaxDynamicSharedMemorySize, SMEM_GEMM);
    cudaFuncSetAttribute(mma_gemm<3>, cudaFuncAttributeMaxDynamicSharedMemorySize, SMEM_GEMM);
    cudaFuncSetAttribute(mma_gemm<6>, cudaFuncAttributeMaxDynamicSharedMemorySize, SMEM_GEMM);
    cudaFuncSetAttribute(mma_gemm<7>, cudaFuncAttributeMaxDynamicSharedMemorySize, SMEM_GEMM);

    // launch 0: round x
    rna4_kernel<<<4096, 256>>>(x, xr_p, NTOK * NDIM / 4);
    // launch 1: consolidated prep (round w/pw/pm, zero kvT, init vT rows 64..79)
    prep_kernel<<<2048, 256>>>(qkv_w, proj_w, proj_mat);

    // launch 2: K1 qkv = xr @ qkv_w^T + b; scatter q,k rounded + v^T rounded
    mma_gemm<2><<<dim3(18, NTOK / 128), 128, SMEM_GEMM>>>(
        xr_p, NDIM, 0, wr_p, NDIM, 0, nullptr, 0, qkv_b, NDIM);

    // launch 3: merged K2: z=0 -> q_p (g_qp), z=1 -> k_p^T (g_kpT)
    mma_gemm<7><<<dim3(2, NRH / 128, 2), 128, SMEM_GEMM>>>(
        qk_p, ND, (size_t)NRH * ND, pmr_p, ND, 0, nullptr, 0, nullptr, ND);

    // launch 4: K3: kv^T[bh] = (vT · kpT^T), split-K=8, atomic fp32 -> g_kvT
    mma_gemm<6><<<dim3(2, 1, NB * NH * 8), 128, SMEM_GEMM>>>(
        nullptr, NL, 0, nullptr, NL, 0, nullptr, 0, nullptr, 512);

    // launch 5: round kvT in place (K4 operand)
    const int kvn = NB * NH * 128 * NM;
    rna4_kernel<<<768, 256>>>(kvt_p, kvt_p, kvn / 4);

    // launch 6: K4: att = (q_p @ kv) / den -> g_att; z = bh
    mma_gemm<3><<<dim3(1, NL / 128, NB * NH), 128, SMEM_GEMM>>>(
        qp_p, NM, (size_t)NL * NM, kvt_p, NM, (size_t)128 * NM,
        nullptr, 0, nullptr, NM);

    // launch 7: K5: out = att @ proj_w^T + proj_b
    mma_gemm<0><<<dim3(NDIM / 128, NTOK / 128), 128, SMEM_GEMM>>>(
        att_p, NDIM, 0, pwr_p, NDIM, 0, out, NDIM, proj_b, NDIM);
}

// round 16
// speedup vs baseline: 1.1066x; 1.0667x over previous
#include <cuda_runtime.h>
#include <cstdint>

// ---------------- problem constants ----------------
#define NB   8
#define NL   4096
#define NDIM 768
#define NH   12
#define ND   64
#define NM   256
#define NTOK (NB * NL)     // 32768
#define NRH  (NTOK * NH)   // 393216
#define FEPS 1.0e-3f
#define RATIO 0.0625f

// ---------------- scratch (static device globals; no allocs) ----------------
__device__ __align__(128) float g_xr [(size_t)NTOK * NDIM];          // 100 MB  x tf32-rounded
__device__ __align__(128) float g_wr [(size_t)2304 * NDIM];          // 7 MB
__device__ __align__(128) float g_pwr[(size_t)NDIM * NDIM];          // 2.4 MB
__device__ __align__(128) float g_pmr[(size_t)NM * ND];              // 64 KB
__device__ __align__(128) float g_qk [(size_t)2 * NRH * ND];         // 200 MB  q|k rounded [sel][bh,l][64]
__device__ __align__(128) float g_qp [(size_t)NRH * NM];             // 402 MB  q_p rounded [bh,l][256]
__device__ __align__(128) float g_kpT[(size_t)NB * NH * NM * NL];    // 402 MB  k_p^T rounded [bh][m][l]
__device__ __align__(128) float g_vT [(size_t)NB * NH * 128 * NL];   // 200 MB  v^T rounded [bh][d|1|0][l]
__device__ __align__(128) float g_kvT[(size_t)NB * NH * 128 * NM];   // 12.6 MB kv^T [bh][n][m] (rna'd in place)
__device__ __align__(128) float g_att[(size_t)NTOK * NDIM];          // 100 MB  att rounded

// ---------------- PTX helpers ----------------
__device__ __forceinline__ uint32_t s2u(const void* p) {
    uint32_t a;
    asm("{ .reg .u64 t; cvta.to.shared.u64 t, %1; cvt.u32.u64 %0, t; }" : "=r"(a) : "l"(p));
    return a;
}
__device__ __forceinline__ void cpa16(uint32_t s, const void* g) {
    asm volatile("cp.async.cg.shared.global [%0], [%1], 16;\n" :: "r"(s), "l"(g));
}
#define CP_COMMIT() asm volatile("cp.async.commit_group;\n" ::: "memory")
#define CP_WAIT(n)  asm volatile("cp.async.wait_group %0;\n" :: "n"(n) : "memory")
#define SW128(o) ((o) ^ (((o) >> 3) & 0x70))

__device__ __forceinline__ void ldsm_x4(uint32_t* r, uint32_t addr) {
    asm volatile("ldmatrix.sync.aligned.m8n8.x4.shared.b16 {%0,%1,%2,%3}, [%4];"
                 : "=r"(r[0]), "=r"(r[1]), "=r"(r[2]), "=r"(r[3]) : "r"(addr));
}
__device__ __forceinline__ void mma_tf32(float* d, const uint32_t* a, uint32_t b0, uint32_t b1) {
    asm volatile(
        "mma.sync.aligned.m16n8k8.row.col.f32.tf32.tf32.f32 "
        "{%0,%1,%2,%3}, {%4,%5,%6,%7}, {%8,%9}, {%0,%1,%2,%3};"
        : "+f"(d[0]), "+f"(d[1]), "+f"(d[2]), "+f"(d[3])
        : "r"(a[0]), "r"(a[1]), "r"(a[2]), "r"(a[3]), "r"(b0), "r"(b1));
}
__device__ __forceinline__ float rna(float v) {
    uint32_t u;
    asm("cvt.rna.tf32.f32 %0, %1;" : "=r"(u) : "f"(v));
    return __uint_as_float(u);
}

// ---------------- fp32 -> tf32-rounded (RNA); src==dst allowed ----------------
__global__ void rna4_kernel(const float* __restrict__ src, float* __restrict__ dst, int total4) {
    for (int i = blockIdx.x * blockDim.x + threadIdx.x; i < total4; i += gridDim.x * blockDim.x) {
        float4 v = *(const float4*)(src + (size_t)i * 4);
        v.x = rna(v.x); v.y = rna(v.y); v.z = rna(v.z); v.w = rna(v.w);
        *(float4*)(dst + (size_t)i * 4) = v;
    }
}

// ---------------- consolidated prep: round w/pw/pm, zero kvT, init vT rows ----------------
#define W4   (2304 * NDIM / 4)            // 442368
#define PW4  (NDIM * NDIM / 4)            // 147456
#define PM4  (NM * ND / 4)                // 4096
#define KV4  (NB * NH * 128 * NM / 4)     // 786432
#define VT4  (NB * NH * 16 * (NL / 4))    // 1572864
#define PREP_TOT (W4 + PW4 + PM4 + KV4 + VT4)

__global__ void prep_kernel(const float* __restrict__ qkv_w,
                            const float* __restrict__ proj_w,
                            const float* __restrict__ proj_mat) {
    for (int i = blockIdx.x * blockDim.x + threadIdx.x; i < PREP_TOT; i += gridDim.x * blockDim.x) {
        if (i < W4) {
            float4 v = *(const float4*)(qkv_w + (size_t)i * 4);
            v.x = rna(v.x); v.y = rna(v.y); v.z = rna(v.z); v.w = rna(v.w);
            *(float4*)(g_wr + (size_t)i * 4) = v;
        } else if (i < W4 + PW4) {
            int j = i - W4;
            float4 v = *(const float4*)(proj_w + (size_t)j * 4);
            v.x = rna(v.x); v.y = rna(v.y); v.z = rna(v.z); v.w = rna(v.w);
            *(float4*)(g_pwr + (size_t)j * 4) = v;
        } else if (i < W4 + PW4 + PM4) {
            int j = i - W4 - PW4;
            float4 v = *(const float4*)(proj_mat + (size_t)j * 4);
            v.x = rna(v.x); v.y = rna(v.y); v.z = rna(v.z); v.w = rna(v.w);
            *(float4*)(g_pmr + (size_t)j * 4) = v;
        } else if (i < W4 + PW4 + PM4 + KV4) {
            int j = i - W4 - PW4 - PM4;
            *(float4*)(g_kvT + (size_t)j * 4) = make_float4(0.f, 0.f, 0.f, 0.f);
        } else {
            int j = i - W4 - PW4 - PM4 - KV4;   // [96][16][1024 float4s]
            int lp = j & (NL / 4 - 1);
            int rp = j >> 10;
            int row = rp & 15;
            int bh = rp >> 4;
            float v = (row == 0) ? 1.0f : 0.0f;
            *(float4*)(g_vT + ((size_t)bh * 128 + 64 + row) * NL + lp * 4) = make_float4(v, v, v, v);
        }
    }
}

// ---------------- 1xTF32 GEMM via mma.sync ----------------
// Tile BM=BN=128, BK=32 fp32. 128 thr = 4 warps (2m x 2n), warp tile 64x64.
// 3-stage cp.async, distance-2 prefetch, single sync per chunk,
// per-warp fragment double-buffering. SW128 smem, ldmatrix.
// Transpose epilogues (kpT, vT) stage via smem st[cl][row] (stride 132,
// conflict-free both phases) and drain with lane-contiguous 512B row stores.
// MODE 0: C = acc + bias (final)                        [K5]
// MODE 2: qkv scatter: q,k rounded -> g_qk; v^T -> g_vT [K1]
// MODE 3: attn: den=col64, divide, rounded -> g_att     [K4]
// MODE 6: kv^T split-K atomic accumulate -> g_kvT       [K3]
// MODE 7: merged K2: z=0 -> q_p (g_qp); z=1 -> k_p^T (g_kpT)
template <int MODE>
__global__ __launch_bounds__(128, 2) void mma_gemm(
    const float* __restrict__ A, int lda, size_t aZ,
    const float* __restrict__ B, int ldb, size_t bZ,
    float* __restrict__ C, int ldc,
    const float* __restrict__ bias,
    int kdim)
{
    extern __shared__ char dynsm[];
    __shared__ float den_sh[128];
    const uint32_t sbase = (s2u(dynsm) + 1023u) & ~1023u;
    const int tid = threadIdx.x;
    const int wid = tid >> 5, lid = tid & 31;
    const int wm = wid & 1, wn = wid >> 1;
    const int n0 = blockIdx.x * 128;
    const int m0 = blockIdx.y * 128;
    int kv_bh = 0;
    if (MODE == 6) {
        kv_bh = blockIdx.z >> 3;
        int seg = blockIdx.z & 7;
        A = g_vT  + (size_t)kv_bh * 128 * NL + seg * 512;   // rows = n (128)
        B = g_kpT + (size_t)kv_bh * NM * NL  + seg * 512;   // rows = m (256, 2 x-tiles)
    } else {
        A += (size_t)blockIdx.z * aZ;
        B += (size_t)blockIdx.z * bZ;
    }
    const int NC = kdim >> 5;

    float acc[4][8][4];
#pragma unroll
    for (int i = 0; i < 4; i++)
#pragma unroll
        for (int j = 0; j < 8; j++)
#pragma unroll
            for (int q = 0; q < 4; q++) acc[i][j][q] = 0.0f;

    auto load_chunk = [&](int c) {
        int slot = c % 3;
        uint32_t ab = sbase + (uint32_t)slot * 32768u;
        uint32_t bb = ab + 16384u;
        const float* ap = A + (size_t)m0 * lda + c * 32;
        const float* bp = B + (size_t)n0 * ldb + c * 32;
#pragma unroll
        for (int i = 0; i < 8; i++) {
            int idx = tid + (i << 7);
            int row = idx >> 3, ch = idx & 7;
            cpa16(ab + SW128(row * 128 + ch * 16), ap + (size_t)row * lda + ch * 4);
        }
#pragma unroll
        for (int i = 0; i < 8; i++) {
            int idx = tid + (i << 7);
            int row = idx >> 3, ch = idx & 7;
            cpa16(bb + SW128(row * 128 + ch * 16), bp + (size_t)row * ldb + ch * 4);
        }
    };

    // preload chunks 0,1 (distance-2 pipeline)
    load_chunk(0); CP_COMMIT();
    if (NC > 1) { load_chunk(1); CP_COMMIT(); }

    const int lt = lid >> 3;
    const int lr = lid & 7;
    const int rowa0 = wm * 64 + ((lt & 1) << 3) + lr;
    const int byta  = (lt >> 1) * 16;
    const int rowb0 = wn * 64 + ((lt >> 1) << 3) + lr;
    const int bytb  = (lt & 1) * 16;

    uint32_t afr[2][4][4], bfr[2][4][4];
    auto ld_frags = [&](uint32_t ab, uint32_t bb, int ks, int buf) {
#pragma unroll
        for (int mi = 0; mi < 4; mi++) {
            int off = (rowa0 + mi * 16) * 128 + ks * 32 + byta;
            ldsm_x4(afr[buf][mi], ab + SW128(off));
        }
#pragma unroll
        for (int ng = 0; ng < 4; ng++) {
            int off = (rowb0 + ng * 16) * 128 + ks * 32 + bytb;
            ldsm_x4(bfr[buf][ng], bb + SW128(off));
        }
    };

    for (int c = 0; c < NC; c++) {
        if (c == NC - 1) { CP_WAIT(0); } else { CP_WAIT(1); }
        __syncthreads();   // single barrier: everyone done reading slot (c-1)%3
        if (c + 2 < NC) { load_chunk(c + 2); CP_COMMIT(); }

        uint32_t ab = sbase + (uint32_t)(c % 3) * 32768u;
        uint32_t bb = ab + 16384u;
        ld_frags(ab, bb, 0, 0);
#pragma unroll
        for (int ks = 0; ks < 4; ks++) {
            int cur = ks & 1;
            if (ks < 3) ld_frags(ab, bb, ks + 1, cur ^ 1);
#pragma unroll
            for (int mi = 0; mi < 4; mi++)
#pragma unroll
                for (int ni = 0; ni < 8; ni++)
                    mma_tf32(acc[mi][ni], afr[cur][mi],
                             bfr[cur][ni >> 1][(ni & 1) * 2], bfr[cur][ni >> 1][(ni & 1) * 2 + 1]);
        }
    }

    // ---------------- epilogue ----------------
    const int lrow = lid >> 2;
    const int lcol = (lid & 3) * 2;

    if (MODE == 0) {
#pragma unroll
        for (int mi = 0; mi < 4; mi++) {
#pragma unroll
            for (int ni = 0; ni < 8; ni++) {
                int col = n0 + wn * 64 + ni * 8 + lcol;
                float b0 = bias[col], b1 = bias[col + 1];
                int r0 = m0 + wm * 64 + mi * 16 + lrow;
                *(float2*)(C + (size_t)r0 * ldc + col) =
                    make_float2(acc[mi][ni][0] + b0, acc[mi][ni][1] + b1);
                *(float2*)(C + (size_t)(r0 + 8) * ldc + col) =
                    make_float2(acc[mi][ni][2] + b0, acc[mi][ni][3] + b1);
            }
        }
    } else if (MODE == 7) {
        if (blockIdx.z == 0) {
            // q_p -> g_qp (rounded); 32B-sector-aligned, already efficient
#pragma unroll
            for (int mi = 0; mi < 4; mi++) {
#pragma unroll
                for (int rr = 0; rr < 2; rr++) {
                    int r = m0 + wm * 64 + mi * 16 + rr * 8 + lrow;
                    float* dst = g_qp + (size_t)r * NM;
#pragma unroll
                    for (int ni = 0; ni < 8; ni++) {
                        int m = n0 + wn * 64 + ni * 8 + lcol;
                        float v0 = rna(fmaxf(acc[mi][ni][rr * 2]     * RATIO, 0.0f) + FEPS);
                        float v1 = rna(fmaxf(acc[mi][ni][rr * 2 + 1] * RATIO, 0.0f) + FEPS);
                        *(float2*)(dst + m) = make_float2(v0, v1);
                    }
                }
            }
        } else {
            // k_p transposed -> g_kpT[bh][m][l]; smem st[cl][row], coalesced drain
            __syncthreads();
            float* st = (float*)dynsm;   // [128 cl][132 row-stride]
#pragma unroll
            for (int mi = 0; mi < 4; mi++) {
#pragma unroll
                for (int rr = 0; rr < 2; rr++) {
                    int row = wm * 64 + mi * 16 + rr * 8 + lrow;
#pragma unroll
                    for (int ni = 0; ni < 8; ni++) {
                        int cl = wn * 64 + ni * 8 + lcol;
                        st[cl * 132 + row] =
                            rna(fmaxf(acc[mi][ni][rr * 2]     * RATIO, 0.0f) + FEPS);
                        st[(cl + 1) * 132 + row] =
                            rna(fmaxf(acc[mi][ni][rr * 2 + 1] * RATIO, 0.0f) + FEPS);
                    }
                }
            }
            __syncthreads();
            int bh = m0 >> 12, l0 = m0 & (NL - 1);
            float* dstb = g_kpT + ((size_t)bh * NM + n0 + wid * 32) * NL + l0 + lid * 4;
            const float* stb = st + (wid * 32) * 132 + lid * 4;
#pragma unroll
            for (int it = 0; it < 32; it++) {
                float4 o = *(const float4*)(stb + it * 132);
                *(float4*)(dstb + (size_t)it * NL) = o;
            }
        }
    } else if (MODE == 2) {
        const int region = n0 / 768;               // 0=q, 1=k, 2=v
        if (region < 2) {
            const int h = ((n0 % 768) >> 6) + wn;
#pragma unroll
            for (int mi = 0; mi < 4; mi++) {
#pragma unroll
                for (int rr = 0; rr < 2; rr++) {
                    int r = m0 + wm * 64 + mi * 16 + rr * 8 + lrow;
                    int b = r >> 12, l = r & (NL - 1);
                    float* dst = g_qk +
                        ((size_t)region * NRH + (size_t)(b * NH + h) * NL + l) * ND;
#pragma unroll
                    for (int ni = 0; ni < 8; ni++) {
                        int d = ni * 8 + lcol;
                        int col = n0 + wn * 64 + d;
                        float v0 = rna(acc[mi][ni][rr * 2]     + bias[col]);
                        float v1 = rna(acc[mi][ni][rr * 2 + 1] + bias[col + 1]);
                        *(float2*)(dst + d) = make_float2(v0, v1);
                    }
                }
            }
        } else {
            // v transposed -> g_vT[bh][d][l]; smem st[cl][row], coalesced drain
            __syncthreads();
            float* st = (float*)dynsm;   // [128 cl][132 row-stride]
#pragma unroll
            for (int mi = 0; mi < 4; mi++) {
#pragma unroll
                for (int rr = 0; rr < 2; rr++) {
                    int row = wm * 64 + mi * 16 + rr * 8 + lrow;
#pragma unroll
                    for (int ni = 0; ni < 8; ni++) {
                        int cl = wn * 64 + ni * 8 + lcol;
                        int col = n0 + cl;
                        st[cl * 132 + row]       = rna(acc[mi][ni][rr * 2]     + bias[col]);
                        st[(cl + 1) * 132 + row] = rna(acc[mi][ni][rr * 2 + 1] + bias[col + 1]);
                    }
                }
            }
            __syncthreads();
            int b = m0 >> 12, l0 = m0 & (NL - 1);
            const int hbase = (n0 - 1536) >> 6;
#pragma unroll
            for (int it = 0; it < 32; it++) {
                int cl = wid * 32 + it;
                int head = hbase + (cl >> 6);
                int d = cl & 63;
                float4 o = *(const float4*)(st + cl * 132 + lid * 4);
                *(float4*)(g_vT + ((size_t)(b * NH + head) * 128 + d) * NL + l0 + lid * 4) = o;
            }
        }
    } else if (MODE == 6) {
        // C = kv^T [n][m]: rows = n, cols = m (n0 selects half of 256)
        float* dst = g_kvT + (size_t)kv_bh * 128 * NM;
#pragma unroll
        for (int mi = 0; mi < 4; mi++) {
#pragma unroll
            for (int ni = 0; ni < 8; ni++) {
                int colx = n0 + wn * 64 + ni * 8 + lcol;
                int r0 = wm * 64 + mi * 16 + lrow;
                atomicAdd(dst + (size_t)r0 * NM + colx,           acc[mi][ni][0]);
                atomicAdd(dst + (size_t)r0 * NM + colx + 1,       acc[mi][ni][1]);
                atomicAdd(dst + (size_t)(r0 + 8) * NM + colx,     acc[mi][ni][2]);
                atomicAdd(dst + (size_t)(r0 + 8) * NM + colx + 1, acc[mi][ni][3]);
            }
        }
    } else if (MODE == 3) {
        // attn: den = col 64 (wn==1, ni==0, lcol==0), divide, write g_att
        if (wn == 1 && (lid & 3) == 0) {
#pragma unroll
            for (int mi = 0; mi < 4; mi++)
#pragma unroll
                for (int rr = 0; rr < 2; rr++)
                    den_sh[wm * 64 + mi * 16 + rr * 8 + lrow] = acc[mi][0][rr * 2];
        }
        __syncthreads();
        if (wn == 0) {
            const int bh = blockIdx.z;
            const int b = bh / NH, h = bh - b * NH;
#pragma unroll
            for (int mi = 0; mi < 4; mi++) {
#pragma unroll
                for (int rr = 0; rr < 2; rr++) {
                    int rloc = wm * 64 + mi * 16 + rr * 8 + lrow;
                    int token = b * NL + m0 + rloc;
                    float inv = 1.0f / den_sh[rloc];
                    float* dst = g_att + (size_t)token * NDIM + h * ND;
#pragma unroll
                    for (int ni = 0; ni < 8; ni++) {
                        int d = ni * 8 + lcol;
                        float v0 = rna(acc[mi][ni][rr * 2]     * inv);
                        float v1 = rna(acc[mi][ni][rr * 2 + 1] * inv);
                        *(float2*)(dst + d) = make_float2(v0, v1);
                    }
                }
            }
        }
    }
}

// ---------------- launch ----------------
extern "C" void kernel_launch(void* const* d_in, const int* in_sizes, int n_in,
                              void* d_out, int out_size)
{
    const float* x        = (const float*)d_in[0];
    const float* qkv_w    = (const float*)d_in[1];
    const float* qkv_b    = (const float*)d_in[2];
    const float* proj_w   = (const float*)d_in[3];
    const float* proj_b   = (const float*)d_in[4];
    const float* proj_mat = (const float*)d_in[5];
    float* out = (float*)d_out;

    float *xr_p, *wr_p, *pwr_p, *pmr_p, *qk_p, *qp_p, *kvt_p, *att_p;
    cudaGetSymbolAddress((void**)&xr_p,  g_xr);
    cudaGetSymbolAddress((void**)&wr_p,  g_wr);
    cudaGetSymbolAddress((void**)&pwr_p, g_pwr);
    cudaGetSymbolAddress((void**)&pmr_p, g_pmr);
    cudaGetSymbolAddress((void**)&qk_p,  g_qk);
    cudaGetSymbolAddress((void**)&qp_p,  g_qp);
    cudaGetSymbolAddress((void**)&kvt_p, g_kvT);
    cudaGetSymbolAddress((void**)&att_p, g_att);

    const int SMEM_GEMM = 3 * 32768 + 1024;
    cudaFuncSetAttribute(mma_gemm<0>, cudaFuncAttributeMaxDynamicSharedMemorySize, SMEM_GEMM);
    cudaFuncSetAttribute(mma_gemm<2>, cudaFuncAttributeMaxDynamicSharedMemorySize, SMEM_GEMM);
    cudaFuncSetAttribute(mma_gemm<3>, cudaFuncAttributeMaxDynamicSharedMemorySize, SMEM_GEMM);
    cudaFuncSetAttribute(mma_gemm<6>, cudaFuncAttributeMaxDynamicSharedMemorySize, SMEM_GEMM);
    cudaFuncSetAttribute(mma_gemm<7>, cudaFuncAttributeMaxDynamicSharedMemorySize, SMEM_GEMM);

    // launch 0: round x
    rna4_kernel<<<4096, 256>>>(x, xr_p, NTOK * NDIM / 4);
    // launch 1: consolidated prep (round w/pw/pm, zero kvT, init vT rows 64..79)
    prep_kernel<<<2048, 256>>>(qkv_w, proj_w, proj_mat);

    // launch 2: K1 qkv = xr @ qkv_w^T + b; scatter q,k rounded + v^T rounded
    mma_gemm<2><<<dim3(18, NTOK / 128), 128, SMEM_GEMM>>>(
        xr_p, NDIM, 0, wr_p, NDIM, 0, nullptr, 0, qkv_b, NDIM);

    // launch 3: merged K2: z=0 -> q_p (g_qp), z=1 -> k_p^T (g_kpT)
    mma_gemm<7><<<dim3(2, NRH / 128, 2), 128, SMEM_GEMM>>>(
        qk_p, ND, (size_t)NRH * ND, pmr_p, ND, 0, nullptr, 0, nullptr, ND);

    // launch 4: K3: kv^T[bh] = (vT · kpT^T), split-K=8, atomic fp32 -> g_kvT
    mma_gemm<6><<<dim3(2, 1, NB * NH * 8), 128, SMEM_GEMM>>>(
        nullptr, NL, 0, nullptr, NL, 0, nullptr, 0, nullptr, 512);

    // launch 5: round kvT in place (K4 operand)
    const int kvn = NB * NH * 128 * NM;
    rna4_kernel<<<768, 256>>>(kvt_p, kvt_p, kvn / 4);

    // launch 6: K4: att = (q_p @ kv) / den -> g_att; z = bh
    mma_gemm<3><<<dim3(1, NL / 128, NB * NH), 128, SMEM_GEMM>>>(
        qp_p, NM, (size_t)NL * NM, kvt_p, NM, (size_t)128 * NM,
        nullptr, 0, nullptr, NM);

    // launch 7: K5: out = att @ proj_w^T + proj_b
    mma_gemm<0><<<dim3(NDIM / 128, NTOK / 128), 128, SMEM_GEMM>>>(
        att_p, NDIM, 0, pwr_p, NDIM, 0, out, NDIM, proj_b, NDIM);
}

// round 17
// speedup vs baseline: 1.1179x; 1.0102x over previous
#include <cuda_runtime.h>
#include <cstdint>

// ---------------- problem constants ----------------
#define NB   8
#define NL   4096
#define NDIM 768
#define NH   12
#define ND   64
#define NM   256
#define NTOK (NB * NL)     // 32768
#define NRH  (NTOK * NH)   // 393216
#define FEPS 1.0e-3f
#define RATIO 0.0625f

// ---------------- scratch (static device globals; no allocs) ----------------
__device__ __align__(128) float g_xr [(size_t)NTOK * NDIM];          // 100 MB  x tf32-rounded
__device__ __align__(128) float g_wr [(size_t)2304 * NDIM];          // 7 MB
__device__ __align__(128) float g_pwr[(size_t)NDIM * NDIM];          // 2.4 MB
__device__ __align__(128) float g_pmr[(size_t)NM * ND];              // 64 KB
__device__ __align__(128) float g_qk [(size_t)2 * NRH * ND];         // 200 MB  q|k rounded [sel][bh,l][64]
__device__ __align__(128) float g_qp [(size_t)NRH * NM];             // 402 MB  q_p rounded [bh,l][256]
__device__ __align__(128) float g_kpT[(size_t)NB * NH * NM * NL];    // 402 MB  k_p^T rounded [bh][m][l]
__device__ __align__(128) float g_vT [(size_t)NB * NH * 128 * NL];   // 200 MB  v^T rounded [bh][d|1|0][l]
__device__ __align__(128) float g_kvT[(size_t)NB * NH * 128 * NM];   // 12.6 MB kv^T [bh][n][m] (rna'd in place)
__device__ __align__(128) float g_att[(size_t)NTOK * NDIM];          // 100 MB  att rounded

// ---------------- PTX helpers ----------------
__device__ __forceinline__ uint32_t s2u(const void* p) {
    uint32_t a;
    asm("{ .reg .u64 t; cvta.to.shared.u64 t, %1; cvt.u32.u64 %0, t; }" : "=r"(a) : "l"(p));
    return a;
}
__device__ __forceinline__ void cpa16(uint32_t s, const void* g) {
    asm volatile("cp.async.cg.shared.global [%0], [%1], 16;\n" :: "r"(s), "l"(g));
}
#define CP_COMMIT() asm volatile("cp.async.commit_group;\n" ::: "memory")
#define CP_WAIT(n)  asm volatile("cp.async.wait_group %0;\n" :: "n"(n) : "memory")
#define SW128(o) ((o) ^ (((o) >> 3) & 0x70))

__device__ __forceinline__ void ldsm_x4(uint32_t* r, uint32_t addr) {
    asm volatile("ldmatrix.sync.aligned.m8n8.x4.shared.b16 {%0,%1,%2,%3}, [%4];"
                 : "=r"(r[0]), "=r"(r[1]), "=r"(r[2]), "=r"(r[3]) : "r"(addr));
}
__device__ __forceinline__ void mma_tf32(float* d, const uint32_t* a, uint32_t b0, uint32_t b1) {
    asm volatile(
        "mma.sync.aligned.m16n8k8.row.col.f32.tf32.tf32.f32 "
        "{%0,%1,%2,%3}, {%4,%5,%6,%7}, {%8,%9}, {%0,%1,%2,%3};"
        : "+f"(d[0]), "+f"(d[1]), "+f"(d[2]), "+f"(d[3])
        : "r"(a[0]), "r"(a[1]), "r"(a[2]), "r"(a[3]), "r"(b0), "r"(b1));
}
__device__ __forceinline__ float rna(float v) {
    uint32_t u;
    asm("cvt.rna.tf32.f32 %0, %1;" : "=r"(u) : "f"(v));
    return __uint_as_float(u);
}

// ---------------- fp32 -> tf32-rounded (RNA); src==dst allowed ----------------
__global__ void rna4_kernel(const float* __restrict__ src, float* __restrict__ dst, int total4) {
    for (int i = blockIdx.x * blockDim.x + threadIdx.x; i < total4; i += gridDim.x * blockDim.x) {
        float4 v = *(const float4*)(src + (size_t)i * 4);
        v.x = rna(v.x); v.y = rna(v.y); v.z = rna(v.z); v.w = rna(v.w);
        *(float4*)(dst + (size_t)i * 4) = v;
    }
}

// ---------------- consolidated prep: round x/w/pw/pm, zero kvT, init vT rows ----------------
#define X4   (NTOK * NDIM / 4)            // 6291456
#define W4   (2304 * NDIM / 4)            // 442368
#define PW4  (NDIM * NDIM / 4)            // 147456
#define PM4  (NM * ND / 4)                // 4096
#define KV4  (NB * NH * 128 * NM / 4)     // 786432
#define VT4  (NB * NH * 16 * (NL / 4))    // 1572864
#define PREP_TOT (X4 + W4 + PW4 + PM4 + KV4 + VT4)

__global__ void prep_kernel(const float* __restrict__ x,
                            const float* __restrict__ qkv_w,
                            const float* __restrict__ proj_w,
                            const float* __restrict__ proj_mat) {
    for (int i = blockIdx.x * blockDim.x + threadIdx.x; i < PREP_TOT; i += gridDim.x * blockDim.x) {
        if (i < X4) {
            float4 v = *(const float4*)(x + (size_t)i * 4);
            v.x = rna(v.x); v.y = rna(v.y); v.z = rna(v.z); v.w = rna(v.w);
            *(float4*)(g_xr + (size_t)i * 4) = v;
        } else if (i < X4 + W4) {
            int j = i - X4;
            float4 v = *(const float4*)(qkv_w + (size_t)j * 4);
            v.x = rna(v.x); v.y = rna(v.y); v.z = rna(v.z); v.w = rna(v.w);
            *(float4*)(g_wr + (size_t)j * 4) = v;
        } else if (i < X4 + W4 + PW4) {
            int j = i - X4 - W4;
            float4 v = *(const float4*)(proj_w + (size_t)j * 4);
            v.x = rna(v.x); v.y = rna(v.y); v.z = rna(v.z); v.w = rna(v.w);
            *(float4*)(g_pwr + (size_t)j * 4) = v;
        } else if (i < X4 + W4 + PW4 + PM4) {
            int j = i - X4 - W4 - PW4;
            float4 v = *(const float4*)(proj_mat + (size_t)j * 4);
            v.x = rna(v.x); v.y = rna(v.y); v.z = rna(v.z); v.w = rna(v.w);
            *(float4*)(g_pmr + (size_t)j * 4) = v;
        } else if (i < X4 + W4 + PW4 + PM4 + KV4) {
            int j = i - X4 - W4 - PW4 - PM4;
            *(float4*)(g_kvT + (size_t)j * 4) = make_float4(0.f, 0.f, 0.f, 0.f);
        } else {
            int j = i - X4 - W4 - PW4 - PM4 - KV4;   // [96][16][1024 float4s]
            int lp = j & (NL / 4 - 1);
            int rp = j >> 10;
            int row = rp & 15;
            int bh = rp >> 4;
            float v = (row == 0) ? 1.0f : 0.0f;
            *(float4*)(g_vT + ((size_t)bh * 128 + 64 + row) * NL + lp * 4) = make_float4(v, v, v, v);
        }
    }
}

// ---------------- 1xTF32 GEMM via mma.sync (tensor-bound stages) ----------------
// Tile BM=BN=128, BK=32 fp32. 128 thr = 4 warps (2m x 2n), warp tile 64x64.
// 3-stage cp.async, distance-2 prefetch, single sync per chunk,
// per-warp fragment double-buffering. SW128 smem, ldmatrix.
// MODE 0: C = acc + bias (final)                        [K5]
// MODE 2: qkv scatter: q,k rounded -> g_qk; v^T -> g_vT [K1]
// MODE 3: attn: den=col64, divide, rounded -> g_att     [K4]
// MODE 6: kv^T split-K atomic accumulate -> g_kvT       [K3]
template <int MODE>
__global__ __launch_bounds__(128, 2) void mma_gemm(
    const float* __restrict__ A, int lda, size_t aZ,
    const float* __restrict__ B, int ldb, size_t bZ,
    float* __restrict__ C, int ldc,
    const float* __restrict__ bias,
    int kdim)
{
    extern __shared__ char dynsm[];
    __shared__ float den_sh[128];
    const uint32_t sbase = (s2u(dynsm) + 1023u) & ~1023u;
    const int tid = threadIdx.x;
    const int wid = tid >> 5, lid = tid & 31;
    const int wm = wid & 1, wn = wid >> 1;
    const int n0 = blockIdx.x * 128;
    const int m0 = blockIdx.y * 128;
    int kv_bh = 0;
    if (MODE == 6) {
        kv_bh = blockIdx.z >> 3;
        int seg = blockIdx.z & 7;
        A = g_vT  + (size_t)kv_bh * 128 * NL + seg * 512;   // rows = n (128)
        B = g_kpT + (size_t)kv_bh * NM * NL  + seg * 512;   // rows = m (256, 2 x-tiles)
    } else {
        A += (size_t)blockIdx.z * aZ;
        B += (size_t)blockIdx.z * bZ;
    }
    const int NC = kdim >> 5;

    float acc[4][8][4];
#pragma unroll
    for (int i = 0; i < 4; i++)
#pragma unroll
        for (int j = 0; j < 8; j++)
#pragma unroll
            for (int q = 0; q < 4; q++) acc[i][j][q] = 0.0f;

    auto load_chunk = [&](int c) {
        int slot = c % 3;
        uint32_t ab = sbase + (uint32_t)slot * 32768u;
        uint32_t bb = ab + 16384u;
        const float* ap = A + (size_t)m0 * lda + c * 32;
        const float* bp = B + (size_t)n0 * ldb + c * 32;
#pragma unroll
        for (int i = 0; i < 8; i++) {
            int idx = tid + (i << 7);
            int row = idx >> 3, ch = idx & 7;
            cpa16(ab + SW128(row * 128 + ch * 16), ap + (size_t)row * lda + ch * 4);
        }
#pragma unroll
        for (int i = 0; i < 8; i++) {
            int idx = tid + (i << 7);
            int row = idx >> 3, ch = idx & 7;
            cpa16(bb + SW128(row * 128 + ch * 16), bp + (size_t)row * ldb + ch * 4);
        }
    };

    load_chunk(0); CP_COMMIT();
    if (NC > 1) { load_chunk(1); CP_COMMIT(); }

    const int lt = lid >> 3;
    const int lr = lid & 7;
    const int rowa0 = wm * 64 + ((lt & 1) << 3) + lr;
    const int byta  = (lt >> 1) * 16;
    const int rowb0 = wn * 64 + ((lt >> 1) << 3) + lr;
    const int bytb  = (lt & 1) * 16;

    uint32_t afr[2][4][4], bfr[2][4][4];
    auto ld_frags = [&](uint32_t ab, uint32_t bb, int ks, int buf) {
#pragma unroll
        for (int mi = 0; mi < 4; mi++) {
            int off = (rowa0 + mi * 16) * 128 + ks * 32 + byta;
            ldsm_x4(afr[buf][mi], ab + SW128(off));
        }
#pragma unroll
        for (int ng = 0; ng < 4; ng++) {
            int off = (rowb0 + ng * 16) * 128 + ks * 32 + bytb;
            ldsm_x4(bfr[buf][ng], bb + SW128(off));
        }
    };

    for (int c = 0; c < NC; c++) {
        if (c == NC - 1) { CP_WAIT(0); } else { CP_WAIT(1); }
        __syncthreads();
        if (c + 2 < NC) { load_chunk(c + 2); CP_COMMIT(); }

        uint32_t ab = sbase + (uint32_t)(c % 3) * 32768u;
        uint32_t bb = ab + 16384u;
        ld_frags(ab, bb, 0, 0);
#pragma unroll
        for (int ks = 0; ks < 4; ks++) {
            int cur = ks & 1;
            if (ks < 3) ld_frags(ab, bb, ks + 1, cur ^ 1);
#pragma unroll
            for (int mi = 0; mi < 4; mi++)
#pragma unroll
                for (int ni = 0; ni < 8; ni++)
                    mma_tf32(acc[mi][ni], afr[cur][mi],
                             bfr[cur][ni >> 1][(ni & 1) * 2], bfr[cur][ni >> 1][(ni & 1) * 2 + 1]);
        }
    }

    // ---------------- epilogue ----------------
    const int lrow = lid >> 2;
    const int lcol = (lid & 3) * 2;

    if (MODE == 0) {
#pragma unroll
        for (int mi = 0; mi < 4; mi++) {
#pragma unroll
            for (int ni = 0; ni < 8; ni++) {
                int col = n0 + wn * 64 + ni * 8 + lcol;
                float b0 = bias[col], b1 = bias[col + 1];
                int r0 = m0 + wm * 64 + mi * 16 + lrow;
                *(float2*)(C + (size_t)r0 * ldc + col) =
                    make_float2(acc[mi][ni][0] + b0, acc[mi][ni][1] + b1);
                *(float2*)(C + (size_t)(r0 + 8) * ldc + col) =
                    make_float2(acc[mi][ni][2] + b0, acc[mi][ni][3] + b1);
            }
        }
    } else if (MODE == 2) {
        const int region = n0 / 768;               // 0=q, 1=k, 2=v
        if (region < 2) {
            const int h = ((n0 % 768) >> 6) + wn;
#pragma unroll
            for (int mi = 0; mi < 4; mi++) {
#pragma unroll
                for (int rr = 0; rr < 2; rr++) {
                    int r = m0 + wm * 64 + mi * 16 + rr * 8 + lrow;
                    int b = r >> 12, l = r & (NL - 1);
                    float* dst = g_qk +
                        ((size_t)region * NRH + (size_t)(b * NH + h) * NL + l) * ND;
#pragma unroll
                    for (int ni = 0; ni < 8; ni++) {
                        int d = ni * 8 + lcol;
                        int col = n0 + wn * 64 + d;
                        float v0 = rna(acc[mi][ni][rr * 2]     + bias[col]);
                        float v1 = rna(acc[mi][ni][rr * 2 + 1] + bias[col + 1]);
                        *(float2*)(dst + d) = make_float2(v0, v1);
                    }
                }
            }
        } else {
            // v transposed -> g_vT[bh][d][l]; smem st[cl][row], coalesced drain
            __syncthreads();
            float* st = (float*)dynsm;   // [128 cl][132 row-stride]
#pragma unroll
            for (int mi = 0; mi < 4; mi++) {
#pragma unroll
                for (int rr = 0; rr < 2; rr++) {
                    int row = wm * 64 + mi * 16 + rr * 8 + lrow;
#pragma unroll
                    for (int ni = 0; ni < 8; ni++) {
                        int cl = wn * 64 + ni * 8 + lcol;
                        int col = n0 + cl;
                        st[cl * 132 + row]       = rna(acc[mi][ni][rr * 2]     + bias[col]);
                        st[(cl + 1) * 132 + row] = rna(acc[mi][ni][rr * 2 + 1] + bias[col + 1]);
                    }
                }
            }
            __syncthreads();
            int b = m0 >> 12, l0 = m0 & (NL - 1);
            const int hbase = (n0 - 1536) >> 6;
#pragma unroll
            for (int it = 0; it < 32; it++) {
                int cl = wid * 32 + it;
                int head = hbase + (cl >> 6);
                int d = cl & 63;
                float4 o = *(const float4*)(st + cl * 132 + lid * 4);
                *(float4*)(g_vT + ((size_t)(b * NH + head) * 128 + d) * NL + l0 + lid * 4) = o;
            }
        }
    } else if (MODE == 6) {
        float* dst = g_kvT + (size_t)kv_bh * 128 * NM;
#pragma unroll
        for (int mi = 0; mi < 4; mi++) {
#pragma unroll
            for (int ni = 0; ni < 8; ni++) {
                int colx = n0 + wn * 64 + ni * 8 + lcol;
                int r0 = wm * 64 + mi * 16 + lrow;
                atomicAdd(dst + (size_t)r0 * NM + colx,           acc[mi][ni][0]);
                atomicAdd(dst + (size_t)r0 * NM + colx + 1,       acc[mi][ni][1]);
                atomicAdd(dst + (size_t)(r0 + 8) * NM + colx,     acc[mi][ni][2]);
                atomicAdd(dst + (size_t)(r0 + 8) * NM + colx + 1, acc[mi][ni][3]);
            }
        }
    } else if (MODE == 3) {
        if (wn == 1 && (lid & 3) == 0) {
#pragma unroll
            for (int mi = 0; mi < 4; mi++)
#pragma unroll
                for (int rr = 0; rr < 2; rr++)
                    den_sh[wm * 64 + mi * 16 + rr * 8 + lrow] = acc[mi][0][rr * 2];
        }
        __syncthreads();
        if (wn == 0) {
            const int bh = blockIdx.z;
            const int b = bh / NH, h = bh - b * NH;
#pragma unroll
            for (int mi = 0; mi < 4; mi++) {
#pragma unroll
                for (int rr = 0; rr < 2; rr++) {
                    int rloc = wm * 64 + mi * 16 + rr * 8 + lrow;
                    int token = b * NL + m0 + rloc;
                    float inv = 1.0f / den_sh[rloc];
                    float* dst = g_att + (size_t)token * NDIM + h * ND;
#pragma unroll
                    for (int ni = 0; ni < 8; ni++) {
                        int d = ni * 8 + lcol;
                        float v0 = rna(acc[mi][ni][rr * 2]     * inv);
                        float v1 = rna(acc[mi][ni][rr * 2 + 1] * inv);
                        *(float2*)(dst + d) = make_float2(v0, v1);
                    }
                }
            }
        }
    }
}

// ---------------- K2 (memory-bound): 256 thr, 8 warps (4m x 2n), warp tile 32x64 ----------------
// z=0 -> q_p (g_qp, rounded); z=1 -> k_p^T (g_kpT, rounded, coalesced transpose).
// Single-buffered fragments (occupancy over ILP: K2 is DRAM-bound).
__global__ __launch_bounds__(256, 2) void mma_gemm_k2(
    const float* __restrict__ A, size_t aZ, const float* __restrict__ B)
{
    extern __shared__ char dynsm[];
    const uint32_t sbase = (s2u(dynsm) + 1023u) & ~1023u;
    const int tid = threadIdx.x;
    const int wid = tid >> 5, lid = tid & 31;
    const int wm = wid & 3, wn = wid >> 2;
    const int n0 = blockIdx.x * 128;
    const int m0 = blockIdx.y * 128;
    A += (size_t)blockIdx.z * aZ;
    const int NC = 2;   // kdim = 64

    float acc[2][8][4];
#pragma unroll
    for (int i = 0; i < 2; i++)
#pragma unroll
        for (int j = 0; j < 8; j++)
#pragma unroll
            for (int q = 0; q < 4; q++) acc[i][j][q] = 0.0f;

    auto load_chunk = [&](int c) {
        int slot = c % 3;
        uint32_t ab = sbase + (uint32_t)slot * 32768u;
        uint32_t bb = ab + 16384u;
        const float* ap = A + (size_t)m0 * ND + c * 32;
        const float* bp = B + (size_t)n0 * ND + c * 32;
#pragma unroll
        for (int i = 0; i < 4; i++) {
            int idx = tid + (i << 8);
            int row = idx >> 3, ch = idx & 7;
            cpa16(ab + SW128(row * 128 + ch * 16), ap + (size_t)row * ND + ch * 4);
        }
#pragma unroll
        for (int i = 0; i < 4; i++) {
            int idx = tid + (i << 8);
            int row = idx >> 3, ch = idx & 7;
            cpa16(bb + SW128(row * 128 + ch * 16), bp + (size_t)row * ND + ch * 4);
        }
    };

    load_chunk(0); CP_COMMIT();
    load_chunk(1); CP_COMMIT();

    const int lt = lid >> 3;
    const int lr = lid & 7;
    const int rowa0 = wm * 32 + ((lt & 1) << 3) + lr;
    const int byta  = (lt >> 1) * 16;
    const int rowb0 = wn * 64 + ((lt >> 1) << 3) + lr;
    const int bytb  = (lt & 1) * 16;

    uint32_t afr[2][4], bfr[4][4];
    for (int c = 0; c < NC; c++) {
        if (c == NC - 1) { CP_WAIT(0); } else { CP_WAIT(1); }
        __syncthreads();

        uint32_t ab = sbase + (uint32_t)(c % 3) * 32768u;
        uint32_t bb = ab + 16384u;
#pragma unroll
        for (int ks = 0; ks < 4; ks++) {
#pragma unroll
            for (int mi = 0; mi < 2; mi++)
                ldsm_x4(afr[mi], ab + SW128((rowa0 + mi * 16) * 128 + ks * 32 + byta));
#pragma unroll
            for (int ng = 0; ng < 4; ng++)
                ldsm_x4(bfr[ng], bb + SW128((rowb0 + ng * 16) * 128 + ks * 32 + bytb));
#pragma unroll
            for (int mi = 0; mi < 2; mi++)
#pragma unroll
                for (int ni = 0; ni < 8; ni++)
                    mma_tf32(acc[mi][ni], afr[mi],
                             bfr[ni >> 1][(ni & 1) * 2], bfr[ni >> 1][(ni & 1) * 2 + 1]);
        }
    }

    const int lrow = lid >> 2;
    const int lcol = (lid & 3) * 2;

    if (blockIdx.z == 0) {
        // q_p -> g_qp (rounded)
#pragma unroll
        for (int mi = 0; mi < 2; mi++) {
#pragma unroll
            for (int rr = 0; rr < 2; rr++) {
                int r = m0 + wm * 32 + mi * 16 + rr * 8 + lrow;
                float* dst = g_qp + (size_t)r * NM;
#pragma unroll
                for (int ni = 0; ni < 8; ni++) {
                    int m = n0 + wn * 64 + ni * 8 + lcol;
                    float v0 = rna(fmaxf(acc[mi][ni][rr * 2]     * RATIO, 0.0f) + FEPS);
                    float v1 = rna(fmaxf(acc[mi][ni][rr * 2 + 1] * RATIO, 0.0f) + FEPS);
                    *(float2*)(dst + m) = make_float2(v0, v1);
                }
            }
        }
    } else {
        // k_p^T -> g_kpT[bh][m][l]; smem st[cl][row], coalesced drain
        __syncthreads();
        float* st = (float*)dynsm;   // [128 cl][132 row-stride]
#pragma unroll
        for (int mi = 0; mi < 2; mi++) {
#pragma unroll
            for (int rr = 0; rr < 2; rr++) {
                int row = wm * 32 + mi * 16 + rr * 8 + lrow;
#pragma unroll
                for (int ni = 0; ni < 8; ni++) {
                    int cl = wn * 64 + ni * 8 + lcol;
                    st[cl * 132 + row] =
                        rna(fmaxf(acc[mi][ni][rr * 2]     * RATIO, 0.0f) + FEPS);
                    st[(cl + 1) * 132 + row] =
                        rna(fmaxf(acc[mi][ni][rr * 2 + 1] * RATIO, 0.0f) + FEPS);
                }
            }
        }
        __syncthreads();
        int bh = m0 >> 12, l0 = m0 & (NL - 1);
        float* dstb = g_kpT + ((size_t)bh * NM + n0 + wid * 16) * NL + l0 + lid * 4;
        const float* stb = st + (wid * 16) * 132 + lid * 4;
#pragma unroll
        for (int it = 0; it < 16; it++) {
            float4 o = *(const float4*)(stb + it * 132);
            *(float4*)(dstb + (size_t)it * NL) = o;
        }
    }
}

// ---------------- launch ----------------
extern "C" void kernel_launch(void* const* d_in, const int* in_sizes, int n_in,
                              void* d_out, int out_size)
{
    const float* x        = (const float*)d_in[0];
    const float* qkv_w    = (const float*)d_in[1];
    const float* qkv_b    = (const float*)d_in[2];
    const float* proj_w   = (const float*)d_in[3];
    const float* proj_b   = (const float*)d_in[4];
    const float* proj_mat = (const float*)d_in[5];
    float* out = (float*)d_out;

    float *xr_p, *wr_p, *pwr_p, *pmr_p, *qk_p, *qp_p, *kvt_p, *att_p;
    cudaGetSymbolAddress((void**)&xr_p,  g_xr);
    cudaGetSymbolAddress((void**)&wr_p,  g_wr);
    cudaGetSymbolAddress((void**)&pwr_p, g_pwr);
    cudaGetSymbolAddress((void**)&pmr_p, g_pmr);
    cudaGetSymbolAddress((void**)&qk_p,  g_qk);
    cudaGetSymbolAddress((void**)&qp_p,  g_qp);
    cudaGetSymbolAddress((void**)&kvt_p, g_kvT);
    cudaGetSymbolAddress((void**)&att_p, g_att);

    const int SMEM_GEMM = 3 * 32768 + 1024;
    cudaFuncSetAttribute(mma_gemm<0>, cudaFuncAttributeMaxDynamicSharedMemorySize, SMEM_GEMM);
    cudaFuncSetAttribute(mma_gemm<2>, cudaFuncAttributeMaxDynamicSharedMemorySize, SMEM_GEMM);
    cudaFuncSetAttribute(mma_gemm<3>, cudaFuncAttributeMaxDynamicSharedMemorySize, SMEM_GEMM);
    cudaFuncSetAttribute(mma_gemm<6>, cudaFuncAttributeMaxDynamicSharedMemorySize, SMEM_GEMM);
    cudaFuncSetAttribute(mma_gemm_k2, cudaFuncAttributeMaxDynamicSharedMemorySize, SMEM_GEMM);

    // launch 0: consolidated prep (round x/w/pw/pm, zero kvT, init vT rows 64..79)
    prep_kernel<<<4096, 256>>>(x, qkv_w, proj_w, proj_mat);

    // launch 1: K1 qkv = xr @ qkv_w^T + b; scatter q,k rounded + v^T rounded
    mma_gemm<2><<<dim3(18, NTOK / 128), 128, SMEM_GEMM>>>(
        xr_p, NDIM, 0, wr_p, NDIM, 0, nullptr, 0, qkv_b, NDIM);

    // launch 2: merged K2 (256-thr memory-optimized): z=0 -> q_p, z=1 -> k_p^T
    mma_gemm_k2<<<dim3(2, NRH / 128, 2), 256, SMEM_GEMM>>>(
        qk_p, (size_t)NRH * ND, pmr_p);

    // launch 3: K3: kv^T[bh] = (vT · kpT^T), split-K=8, atomic fp32 -> g_kvT
    mma_gemm<6><<<dim3(2, 1, NB * NH * 8), 128, SMEM_GEMM>>>(
        nullptr, NL, 0, nullptr, NL, 0, nullptr, 0, nullptr, 512);

    // launch 4: round kvT in place (K4 operand)
    const int kvn = NB * NH * 128 * NM;
    rna4_kernel<<<768, 256>>>(kvt_p, kvt_p, kvn / 4);

    // launch 5: K4: att = (q_p @ kv) / den -> g_att; z = bh
    mma_gemm<3><<<dim3(1, NL / 128, NB * NH), 128, SMEM_GEMM>>>(
        qp_p, NM, (size_t)NL * NM, kvt_p, NM, (size_t)128 * NM,
        nullptr, 0, nullptr, NM);

    // launch 6: K5: out = att @ proj_w^T + proj_b
    mma_gemm<0><<<dim3(NDIM / 128, NTOK / 128), 128, SMEM_GEMM>>>(
        att_p, NDIM, 0, pwr_p, NDIM, 0, out, NDIM, proj_b, NDIM);
}